// round 10
// baseline (speedup 1.0000x reference)
#include <cuda_runtime.h>

// VectorQuantizer on GB300 (sm_103a) — tf32 tensor-core filter + exact rescue.
// Inputs:  d_in[0] = inputs  [16,1024,512] f32   (N = 16384 rows, D = 512)
//          d_in[1] = embedding [8192,512]  f32   (K = 8192 codes)
// Output layout (float32, reference return order):
//   [0:NE) quantized_ste | [NE:2NE) quantized | [2NE] q_loss | [2NE+1] e_loss
//   [2NE+2 : +nrows) indices (as float)
//
// Phase A: mma.sync tf32 computes approx d~ = en - 2*dot~ (xn cancels per row),
//   per-row running min via atomicMin, candidates = { d~ <= runmin + MARGIN }.
// Phase B: exact fp32 chain (sequential over d ascending, fl(fl(xn+en)-2dot),
//   lex-min lowest-index ties) over candidates only — bit-identical decision to
//   the R7 exact kernel (rel_err 0.0). Overflow rows get a full exact scan.
//   Winner membership: |d~ - (d_exact - xn)| <= ~2e-4; MARGIN = 1.5e-3 (~4x).

#define DIMS  512
#define MAXN  16384
#define MAXK  8192
#define CAP   32
#define MARGIN 1.5e-3f

typedef unsigned int u32;

__device__ float g_xnorm[MAXN];
__device__ float g_enorm[MAXK];
__device__ u32   g_rowkey[MAXN];          // order-encoded running min of d~
__device__ int   g_candcnt[MAXN];
__device__ int   g_cand[MAXN * CAP];
__device__ int   g_best[MAXN];
__device__ float g_losspart[MAXN];

__device__ __forceinline__ u32 fkey(float f) {
    int i = __float_as_int(f);
    return (u32)i ^ ((u32)(i >> 31) | 0x80000000u);
}
__device__ __forceinline__ float funkey(u32 k) {
    int i = (k & 0x80000000u) ? (int)(k ^ 0x80000000u) : (int)(~k);
    return __int_as_float(i);
}

// ---------------------------------------------------------------------------
__global__ void init_kernel(void)
{
    int i = blockIdx.x * blockDim.x + threadIdx.x;
    if (i < MAXN) { g_candcnt[i] = 0; g_rowkey[i] = 0xFFFFFFFFu; }
}

// ---------------------------------------------------------------------------
__global__ void row_norm_kernel(const float* __restrict__ src, int which)
{
    int row = blockIdx.x;
    const float4 v = reinterpret_cast<const float4*>(src + (size_t)row * DIMS)[threadIdx.x];
    float s = v.x * v.x + v.y * v.y + v.z * v.z + v.w * v.w;

    __shared__ float sm[128];
    sm[threadIdx.x] = s;
    __syncthreads();
    #pragma unroll
    for (int off = 64; off > 0; off >>= 1) {
        if (threadIdx.x < off) sm[threadIdx.x] += sm[threadIdx.x + off];
        __syncthreads();
    }
    if (threadIdx.x == 0) {
        if (which) g_enorm[row] = sm[0];
        else       g_xnorm[row] = sm[0];
    }
}

// ---------------------------------------------------------------------------
// Phase A: tf32 mma filter. Grid (nrows/128, 16). 256 threads = 8 warps in
// 4(m) x 2(n); warp tile 32 rows x 64 codes; CTA tile 128 x 128 per k-tile,
// 4 k-tiles per CTA (k-range 512). d-chunks of 16 via 2-stage cp.async.
// smem stride 20 floats -> conflict-free fragment loads (full bank permutation).
// ---------------------------------------------------------------------------
#define ACHUNKS 128   // 4 ktiles * 32 d-chunks

__global__ __launch_bounds__(256, 2)
void tf32_filter_kernel(const float* __restrict__ X, const float* __restrict__ E)
{
    __shared__ float Xs[2][128][20];
    __shared__ float Es[2][128][20];

    const int tid  = threadIdx.x;
    const int lane = tid & 31;
    const int wid  = tid >> 5;
    const int wm   = wid >> 1;          // 0..3
    const int wn   = wid & 1;           // 0..1
    const int g    = lane >> 2;         // groupID 0..7
    const int tig  = lane & 3;          // 0..3

    const int rowBase = blockIdx.x * 128;
    const int kBase   = blockIdx.y * 512;

    // loader mapping: row = tid>>1, d-offset (tid&1)*8, two 16B cp.asyncs each array
    const int lrow = tid >> 1;
    const int ld0  = (tid & 1) * 8;

    const u32 xs_base = (u32)__cvta_generic_to_shared(&Xs[0][0][0]);
    const u32 es_base = (u32)__cvta_generic_to_shared(&Es[0][0][0]);
    const u32 smem_off = (u32)((lrow * 20 + ld0) * 4);
    const u32 buf_stride = 128u * 20u * 4u;

    float acc[2][8][4];
    #pragma unroll
    for (int mt = 0; mt < 2; mt++)
        #pragma unroll
        for (int nt = 0; nt < 8; nt++)
            #pragma unroll
            for (int r = 0; r < 4; r++) acc[mt][nt][r] = 0.0f;

    // issue chunk 0
    {
        const float* gx = X + (size_t)(rowBase + lrow) * DIMS + ld0;
        const float* ge = E + (size_t)(kBase + lrow) * DIMS + ld0;
        asm volatile("cp.async.cg.shared.global [%0], [%1], 16;" :: "r"(xs_base + smem_off), "l"(gx));
        asm volatile("cp.async.cg.shared.global [%0], [%1], 16;" :: "r"(xs_base + smem_off + 16), "l"(gx + 4));
        asm volatile("cp.async.cg.shared.global [%0], [%1], 16;" :: "r"(es_base + smem_off), "l"(ge));
        asm volatile("cp.async.cg.shared.global [%0], [%1], 16;" :: "r"(es_base + smem_off + 16), "l"(ge + 4));
        asm volatile("cp.async.commit_group;");
    }

    for (int c = 0; c < ACHUNKS; c++) {
        asm volatile("cp.async.wait_group 0;");
        __syncthreads();             // chunk c visible; all threads done with chunk c-1's buffer

        const int p = c & 1;

        if (c + 1 < ACHUNKS) {       // issue chunk c+1 into the other buffer
            const int nc = c + 1;
            const int nkt = nc >> 5;
            const int ndc = (nc & 31) * 16;
            const u32 doff = (u32)((nc & 1) ? buf_stride : 0) + smem_off;
            const float* gx = X + (size_t)(rowBase + lrow) * DIMS + ndc + ld0;
            const float* ge = E + (size_t)(kBase + nkt * 128 + lrow) * DIMS + ndc + ld0;
            asm volatile("cp.async.cg.shared.global [%0], [%1], 16;" :: "r"(xs_base + doff), "l"(gx));
            asm volatile("cp.async.cg.shared.global [%0], [%1], 16;" :: "r"(xs_base + doff + 16), "l"(gx + 4));
            asm volatile("cp.async.cg.shared.global [%0], [%1], 16;" :: "r"(es_base + doff), "l"(ge));
            asm volatile("cp.async.cg.shared.global [%0], [%1], 16;" :: "r"(es_base + doff + 16), "l"(ge + 4));
            asm volatile("cp.async.commit_group;");
        } else {
            asm volatile("cp.async.commit_group;");   // keep wait_group counts consistent
        }

        // ---- compute chunk c: 2 k8-steps of 16 mma ----
        #pragma unroll
        for (int ks = 0; ks < 2; ks++) {
            const int k0 = ks * 8;
            u32 af[2][4];
            #pragma unroll
            for (int mt = 0; mt < 2; mt++) {
                const int r = wm * 32 + mt * 16;
                af[mt][0] = __float_as_uint(Xs[p][r + g][k0 + tig]);
                af[mt][1] = __float_as_uint(Xs[p][r + g + 8][k0 + tig]);
                af[mt][2] = __float_as_uint(Xs[p][r + g][k0 + tig + 4]);
                af[mt][3] = __float_as_uint(Xs[p][r + g + 8][k0 + tig + 4]);
            }
            #pragma unroll
            for (int nt = 0; nt < 8; nt++) {
                const int cn = wn * 64 + nt * 8;
                u32 b0 = __float_as_uint(Es[p][cn + g][k0 + tig]);
                u32 b1 = __float_as_uint(Es[p][cn + g][k0 + tig + 4]);
                #pragma unroll
                for (int mt = 0; mt < 2; mt++) {
                    asm volatile(
                        "mma.sync.aligned.m16n8k8.row.col.f32.tf32.tf32.f32 "
                        "{%0,%1,%2,%3}, {%4,%5,%6,%7}, {%8,%9}, {%0,%1,%2,%3};"
                        : "+f"(acc[mt][nt][0]), "+f"(acc[mt][nt][1]),
                          "+f"(acc[mt][nt][2]), "+f"(acc[mt][nt][3])
                        : "r"(af[mt][0]), "r"(af[mt][1]), "r"(af[mt][2]), "r"(af[mt][3]),
                          "r"(b0), "r"(b1));
                }
            }
        }

        // ---- k-tile epilogue: running min + candidate append ----
        if ((c & 31) == 31) {
            const int kt = c >> 5;
            const int kcol0 = kBase + kt * 128 + wn * 64;

            float enr[8][2];
            #pragma unroll
            for (int nt = 0; nt < 8; nt++) {
                enr[nt][0] = g_enorm[kcol0 + nt * 8 + tig * 2];
                enr[nt][1] = g_enorm[kcol0 + nt * 8 + tig * 2 + 1];
            }

            #pragma unroll
            for (int s = 0; s < 4; s++) {
                const int mt = s >> 1, hf = s & 1;
                const int grow = rowBase + wm * 32 + mt * 16 + hf * 8 + g;

                float lv = 3.402823466e38f;
                int   li = 0x7fffffff;
                #pragma unroll
                for (int nt = 0; nt < 8; nt++)
                    #pragma unroll
                    for (int h = 0; h < 2; h++) {
                        float dv = fmaf(-2.0f, acc[mt][nt][hf * 2 + h], enr[nt][h]);
                        int code = kcol0 + nt * 8 + tig * 2 + h;
                        if (dv < lv || (dv == lv && code < li)) { lv = dv; li = code; }
                    }
                #pragma unroll
                for (int off = 1; off < 4; off <<= 1) {
                    float ov = __shfl_xor_sync(0xffffffffu, lv, off);
                    int   oi = __shfl_xor_sync(0xffffffffu, li, off);
                    if (ov < lv || (ov == lv && oi < li)) { lv = ov; li = oi; }
                }
                u32 latestk = 0;
                if (tig == 0) {
                    u32 mk = fkey(lv);
                    u32 old = atomicMin(&g_rowkey[grow], mk);
                    latestk = old < mk ? old : mk;
                }
                latestk = __shfl_sync(0xffffffffu, latestk, lane & ~3);
                const float thresh = funkey(latestk) + MARGIN;

                #pragma unroll
                for (int nt = 0; nt < 8; nt++)
                    #pragma unroll
                    for (int h = 0; h < 2; h++) {
                        float dv = fmaf(-2.0f, acc[mt][nt][hf * 2 + h], enr[nt][h]);
                        if (dv <= thresh) {
                            int code = kcol0 + nt * 8 + tig * 2 + h;
                            int slot = atomicAdd(&g_candcnt[grow], 1);
                            if (slot < CAP) g_cand[grow * CAP + slot] = code;
                        }
                    }
            }
            #pragma unroll
            for (int mt = 0; mt < 2; mt++)
                #pragma unroll
                for (int nt = 0; nt < 8; nt++)
                    #pragma unroll
                    for (int r = 0; r < 4; r++) acc[mt][nt][r] = 0.0f;
        }
    }
}

// ---------------------------------------------------------------------------
// Phase B: exact rescue. One warp per row; lane per candidate. Exact fp32
// sequential-over-d chain, fl(fl(xn+en)-2dot), lex-min lowest index.
// ---------------------------------------------------------------------------
__device__ __forceinline__ float exact_dist(const float* __restrict__ X,
                                            const float* __restrict__ E,
                                            int row, int code, float xn)
{
    const float4* x4 = reinterpret_cast<const float4*>(X + (size_t)row * DIMS);
    const float4* e4 = reinterpret_cast<const float4*>(E + (size_t)code * DIMS);
    float acc = 0.0f;
    #pragma unroll 4
    for (int d4 = 0; d4 < DIMS / 4; d4++) {
        float4 xv = x4[d4];
        float4 ev = e4[d4];
        acc = fmaf(xv.x, ev.x, acc);
        acc = fmaf(xv.y, ev.y, acc);
        acc = fmaf(xv.z, ev.z, acc);
        acc = fmaf(xv.w, ev.w, acc);
    }
    return __fsub_rn(__fadd_rn(xn, g_enorm[code]), 2.0f * acc);
}

__global__ void exact_rescue_kernel(const float* __restrict__ X,
                                    const float* __restrict__ E,
                                    int nrows, int K)
{
    const int w = (blockIdx.x * blockDim.x + threadIdx.x) >> 5;
    if (w >= nrows) return;
    const int lane = threadIdx.x & 31;
    const int row  = w;
    const int cnt  = g_candcnt[row];
    const float xn = g_xnorm[row];

    float bv = 3.402823466e38f;
    int   bi = 0x7fffffff;

    if (cnt <= CAP) {
        if (lane < cnt) {
            int code = g_cand[row * CAP + lane];
            bv = exact_dist(X, E, row, code, xn);
            bi = code;
        }
    } else {
        // overflow: exact full scan (ascending codes per lane; lex merge below)
        for (int code = lane; code < K; code += 32) {
            float dv = exact_dist(X, E, row, code, xn);
            if (dv < bv || (dv == bv && code < bi)) { bv = dv; bi = code; }
        }
    }

    #pragma unroll
    for (int off = 16; off > 0; off >>= 1) {
        float ov = __shfl_xor_sync(0xffffffffu, bv, off);
        int   oi = __shfl_xor_sync(0xffffffffu, bi, off);
        if (ov < bv || (ov == bv && oi < bi)) { bv = ov; bi = oi; }
    }
    if (lane == 0) g_best[row] = bi;
}

// ---------------------------------------------------------------------------
// Gather + STE + loss partials. One block (128 thr) per row.
// ---------------------------------------------------------------------------
__global__ void gather_out_kernel(const float* __restrict__ X, const float* __restrict__ E,
                                  float* __restrict__ out, long long NE, long long outsz)
{
    int row = blockIdx.x;
    int idx = g_best[row];

    float4 x = reinterpret_cast<const float4*>(X + (size_t)row * DIMS)[threadIdx.x];
    float4 e = reinterpret_cast<const float4*>(E + (size_t)idx * DIMS)[threadIdx.x];

    float4 df, st;
    df.x = __fsub_rn(e.x, x.x); st.x = __fadd_rn(x.x, df.x);
    df.y = __fsub_rn(e.y, x.y); st.y = __fadd_rn(x.y, df.y);
    df.z = __fsub_rn(e.z, x.z); st.z = __fadd_rn(x.z, df.z);
    df.w = __fsub_rn(e.w, x.w); st.w = __fadd_rn(x.w, df.w);

    long long base = (long long)row * DIMS + (long long)threadIdx.x * 4;
    if (base + 3 < outsz)
        *reinterpret_cast<float4*>(out + base) = st;
    if (NE + base + 3 < outsz)
        *reinterpret_cast<float4*>(out + NE + base) = e;

    float s = __fmul_rn(df.x, df.x) + __fmul_rn(df.y, df.y)
            + __fmul_rn(df.z, df.z) + __fmul_rn(df.w, df.w);

    __shared__ float sm[128];
    sm[threadIdx.x] = s;
    __syncthreads();
    #pragma unroll
    for (int off = 64; off > 0; off >>= 1) {
        if (threadIdx.x < off) sm[threadIdx.x] += sm[threadIdx.x + off];
        __syncthreads();
    }
    if (threadIdx.x == 0) g_losspart[row] = sm[0];
}

// ---------------------------------------------------------------------------
__global__ void finalize_kernel(float* __restrict__ out, int nrows, long long NE, long long outsz)
{
    __shared__ double sm[256];
    double s = 0.0;
    for (int i = threadIdx.x; i < nrows; i += 256) s += (double)g_losspart[i];
    sm[threadIdx.x] = s;
    __syncthreads();
    #pragma unroll
    for (int off = 128; off > 0; off >>= 1) {
        if (threadIdx.x < off) sm[threadIdx.x] += sm[threadIdx.x + off];
        __syncthreads();
    }
    if (threadIdx.x == 0) {
        float loss = (float)(sm[0] / (double)NE);
        if (2 * NE     < outsz) out[2 * NE]     = loss;
        if (2 * NE + 1 < outsz) out[2 * NE + 1] = loss;
    }
    for (int i = threadIdx.x; i < nrows; i += 256) {
        long long o = 2 * NE + 2 + i;
        if (o < outsz) out[o] = (float)g_best[i];
    }
    for (long long o = 2 * NE + 2 + nrows + threadIdx.x; o < outsz; o += 256)
        out[o] = 0.0f;
}

// ---------------------------------------------------------------------------
extern "C" void kernel_launch(void* const* d_in, const int* in_sizes, int n_in,
                              void* d_out, int out_size)
{
    const float* X = (const float*)d_in[0];
    const float* E = (const float*)d_in[1];

    const long long NE = (long long)in_sizes[0];      // 8388608
    const int nrows    = (int)(NE / DIMS);            // 16384
    const int K        = in_sizes[1] / DIMS;          // 8192
    float* out         = (float*)d_out;
    const long long outsz = (long long)out_size;

    init_kernel<<<(MAXN + 255) / 256, 256>>>();
    row_norm_kernel<<<nrows, 128>>>(X, 0);
    row_norm_kernel<<<K,     128>>>(E, 1);

    dim3 gridA(nrows / 128, 16);
    tf32_filter_kernel<<<gridA, 256>>>(X, E);

    exact_rescue_kernel<<<(nrows * 32 + 255) / 256, 256>>>(X, E, nrows, K);

    gather_out_kernel<<<nrows, 128>>>(X, E, out, NE, outsz);
    finalize_kernel<<<1, 256>>>(out, nrows, NE, outsz);
}